// round 1
// baseline (speedup 1.0000x reference)
#include <cuda_runtime.h>
#include <math.h>
#include <stdint.h>

#define BDIM 384
#define HEADS 8
#define HD 48
#define NSEQ 2048
#define NB 4
#define MROWS (NB*NSEQ)      /* 8192 */
#define MLPH 1536

/* ------------ scratch (device globals; no allocation allowed) ------------ */
__device__ float g_h [MROWS*BDIM];
__device__ float g_q [MROWS*BDIM];
__device__ float g_k [MROWS*BDIM];
__device__ float g_v [MROWS*BDIM];
__device__ float g_pe[MROWS*HD];
__device__ float g_att[MROWS*BDIM];
__device__ float g_x1[MROWS*BDIM];
__device__ float g_hid[MROWS*MLPH];
__device__ int   g_mask[MROWS];

__device__ __forceinline__ float gelu_exact(float x) {
    return 0.5f * x * (1.0f + erff(x * 0.70710678118654752f));
}

/* ------------ mask dtype sniffing + conversion ------------
   jax bool may be delivered as uint8, int32 or float32. Detect from byte
   pattern over the first n bytes (safe under all encodings):
     - any byte 0x3F at offset%4==3  -> float32 (1.0f = 00 00 80 3F)
     - else any nonzero byte at offset%4!=0 -> uint8
     - else int32.                                                    */
__global__ void mask_convert_kernel(const void* __restrict__ mptr, int n,
                                    int* __restrict__ out) {
    const unsigned char* b = (const unsigned char*)mptr;
    __shared__ int f32flag, nm4flag;
    if (threadIdx.x == 0) { f32flag = 0; nm4flag = 0; }
    __syncthreads();
    int lf = 0, ln4 = 0;
    for (int i = threadIdx.x; i < n; i += blockDim.x) {
        unsigned char c = b[i];
        if (c == 0x3Fu && (i & 3) == 3) lf = 1;
        if (c != 0u   && (i & 3) != 0) ln4 = 1;
    }
    if (lf)  atomicOr(&f32flag, 1);
    if (ln4) atomicOr(&nm4flag, 1);
    __syncthreads();
    int mode = f32flag ? 2 : (nm4flag ? 0 : 1);
    for (int i = threadIdx.x; i < n; i += blockDim.x) {
        int v;
        if      (mode == 0) v = (b[i] != 0);
        else if (mode == 1) v = (((const int*)mptr)[i]   != 0);
        else                v = (((const float*)mptr)[i] != 0.0f);
        out[i] = v;
    }
}

/* ------------ LayerNorm over 384 cols, one block per row ------------ */
__device__ __forceinline__ float warp_sum(float v) {
    #pragma unroll
    for (int o = 16; o; o >>= 1) v += __shfl_xor_sync(0xffffffffu, v, o);
    return v;
}

__global__ void ln_kernel(const float* __restrict__ X,
                          const float* __restrict__ g,
                          const float* __restrict__ be,
                          float* __restrict__ Y) {
    int row = blockIdx.x;
    const float* x = X + (size_t)row * BDIM;
    float*       y = Y + (size_t)row * BDIM;
    int t = threadIdx.x;                 /* 128 threads, 3 cols each */
    float v0 = x[t], v1 = x[t + 128], v2 = x[t + 256];
    float s  = v0 + v1 + v2;
    float sq = v0*v0 + v1*v1 + v2*v2;
    s = warp_sum(s); sq = warp_sum(sq);
    __shared__ float ss[4], sqq[4];
    int w = t >> 5, lane = t & 31;
    if (lane == 0) { ss[w] = s; sqq[w] = sq; }
    __syncthreads();
    float S  = ss[0] + ss[1] + ss[2] + ss[3];
    float SQ = sqq[0] + sqq[1] + sqq[2] + sqq[3];
    float mean = S * (1.0f / BDIM);
    float var  = SQ * (1.0f / BDIM) - mean * mean;
    float rstd = rsqrtf(var + 1e-5f);
    y[t      ] = (v0 - mean) * rstd * g[t      ] + be[t      ];
    y[t + 128] = (v1 - mean) * rstd * g[t + 128] + be[t + 128];
    y[t + 256] = (v2 - mean) * rstd * g[t + 256] + be[t + 256];
}

/* ------------ positional MLP: pe = gelu(pos@pw1+pb1)@pw2+pb2 ------------ */
__global__ void pe_kernel(const float* __restrict__ pos,
                          const float* __restrict__ pw1,
                          const float* __restrict__ pb1,
                          const float* __restrict__ pw2,
                          const float* __restrict__ pb2,
                          float* __restrict__ pe) {
    int row = blockIdx.x;
    __shared__ float t[HD];
    int i = threadIdx.x;                  /* 64 threads, 48 active */
    float p0 = pos[row*3], p1 = pos[row*3+1], p2 = pos[row*3+2];
    if (i < HD) {
        float u = p0*pw1[i] + p1*pw1[HD+i] + p2*pw1[2*HD+i] + pb1[i];
        t[i] = gelu_exact(u);
    }
    __syncthreads();
    if (i < HD) {
        float acc = pb2[i];
        #pragma unroll 8
        for (int k = 0; k < HD; k++) acc += t[k] * pw2[k*HD + i];
        pe[(size_t)row*HD + i] = acc;
    }
}

/* ------------ generic 64x64 tiled fp32 GEMM with fused epilogues ------------
   EPI 1: QKV scatter  -> C[((b*8+h)*2048+n)*48+d] = acc+bias (+pe if flag)
   EPI 2: Wo           -> C = (acc+bias)*mask[row] + extra[row,col]
   EPI 3: MLP1         -> C = gelu(acc+bias)
   EPI 4: MLP2         -> C = (acc+bias+extra[row,col])*mask[row]            */
#define BM 64
#define BN 64
#define BK 16

template<int EPI>
__global__ void gemm_kernel(const float* __restrict__ A,
                            const float* __restrict__ W,
                            const float* __restrict__ bias,
                            float* __restrict__ C,
                            int K, int Nc,
                            const float* __restrict__ extra,
                            const int* __restrict__ mask,
                            int flag) {
    __shared__ float As[BK][BM];
    __shared__ float Ws[BK][BN];
    int bm = blockIdx.x * BM;
    int bn = blockIdx.y * BN;
    int tid = threadIdx.x;               /* 256 */
    int tx = tid & 15, ty = tid >> 4;
    int a_r = tid >> 2;                  /* 0..63 */
    int a_k = (tid & 3) * 4;             /* 0,4,8,12 */
    int w_k = tid >> 4;                  /* 0..15 */
    int w_n = (tid & 15) * 4;

    float acc[4][4];
    #pragma unroll
    for (int i = 0; i < 4; i++)
        #pragma unroll
        for (int j = 0; j < 4; j++) acc[i][j] = 0.f;

    const float* aptr = A + (size_t)(bm + a_r) * K + a_k;
    const float* wptr = W + (size_t)w_k * Nc + bn + w_n;

    for (int k0 = 0; k0 < K; k0 += BK) {
        float4 av = *(const float4*)(aptr + k0);
        float4 wv = *(const float4*)(wptr + (size_t)k0 * Nc);
        As[a_k+0][a_r] = av.x; As[a_k+1][a_r] = av.y;
        As[a_k+2][a_r] = av.z; As[a_k+3][a_r] = av.w;
        *(float4*)&Ws[w_k][w_n] = wv;
        __syncthreads();
        #pragma unroll
        for (int k = 0; k < BK; k++) {
            float4 ra = *(const float4*)&As[k][ty*4];
            float4 rb = *(const float4*)&Ws[k][tx*4];
            acc[0][0] += ra.x*rb.x; acc[0][1] += ra.x*rb.y;
            acc[0][2] += ra.x*rb.z; acc[0][3] += ra.x*rb.w;
            acc[1][0] += ra.y*rb.x; acc[1][1] += ra.y*rb.y;
            acc[1][2] += ra.y*rb.z; acc[1][3] += ra.y*rb.w;
            acc[2][0] += ra.z*rb.x; acc[2][1] += ra.z*rb.y;
            acc[2][2] += ra.z*rb.z; acc[2][3] += ra.z*rb.w;
            acc[3][0] += ra.w*rb.x; acc[3][1] += ra.w*rb.y;
            acc[3][2] += ra.w*rb.z; acc[3][3] += ra.w*rb.w;
        }
        __syncthreads();
    }

    #pragma unroll
    for (int i = 0; i < 4; i++) {
        int row = bm + ty*4 + i;
        #pragma unroll
        for (int j = 0; j < 4; j++) {
            int col = bn + tx*4 + j;
            float v = acc[i][j] + bias[col];
            if (EPI == 1) {
                int d = col % HD, hh = col / HD;
                if (flag) v += extra[(size_t)row*HD + d];
                int bb = row >> 11, n = row & (NSEQ-1);
                C[(((size_t)(bb*HEADS + hh))*NSEQ + n)*HD + d] = v;
            } else if (EPI == 2) {
                v *= (float)mask[row];
                v += extra[(size_t)row*Nc + col];
                C[(size_t)row*Nc + col] = v;
            } else if (EPI == 3) {
                C[(size_t)row*Nc + col] = gelu_exact(v);
            } else { /* EPI == 4 */
                v += extra[(size_t)row*Nc + col];
                v *= (float)mask[row];
                C[(size_t)row*Nc + col] = v;
            }
        }
    }
}

/* ------------ flash-style attention, one block per (b,h,q-tile of 64) ----- */
#define QPAD 49
#define SPAD 65
#define ATT_SMEM ((3*64*QPAD + 64*SPAD + 64*4) * 4)

__global__ void attn_kernel(const float* __restrict__ Q,
                            const float* __restrict__ Kb,
                            const float* __restrict__ Vb,
                            const int* __restrict__ mask,
                            float* __restrict__ O) {
    extern __shared__ float sm[];
    float* Qs   = sm;                       /* [64][49] */
    float* Ks   = Qs + 64*QPAD;
    float* Vs   = Ks + 64*QPAD;
    float* Ss   = Vs + 64*QPAD;             /* [64][65] */
    float* rowm = Ss + 64*SPAD;
    float* rowl = rowm + 64;
    float* rowf = rowl + 64;
    int*   km   = (int*)(rowf + 64);

    int bh = blockIdx.y;
    int b  = bh >> 3;
    int h  = bh & 7;
    int q0 = blockIdx.x * 64;
    int tid = threadIdx.x;                  /* 256 */
    const float* qp = Q  + (size_t)bh * NSEQ * HD;
    const float* kp = Kb + (size_t)bh * NSEQ * HD;
    const float* vp = Vb + (size_t)bh * NSEQ * HD;

    /* load Q tile (transposed-padded rows) */
    #pragma unroll
    for (int it = 0; it < 3; it++) {
        int idx = tid + it*256;             /* float4 index 0..767 */
        int r = idx / 12, c4 = (idx % 12) * 4;
        float4 qv = *(const float4*)(qp + (size_t)(q0 + r)*HD + c4);
        float* d = Qs + r*QPAD + c4;
        d[0]=qv.x; d[1]=qv.y; d[2]=qv.z; d[3]=qv.w;
    }
    if (tid < 64) { rowm[tid] = -INFINITY; rowl[tid] = 0.f; }

    int tx = tid & 15, ty = tid >> 4;
    int ty4 = ty*4, tx4 = tx*4, tc3 = tx*3;
    float acc[4][3];
    #pragma unroll
    for (int i = 0; i < 4; i++) { acc[i][0]=0.f; acc[i][1]=0.f; acc[i][2]=0.f; }
    const float scale = 0.14433756729740643f;   /* 48^-0.5 */

    for (int kt = 0; kt < NSEQ/64; kt++) {
        int k0 = kt * 64;
        __syncthreads();      /* previous readers of Ks/Vs done */
        #pragma unroll
        for (int it = 0; it < 3; it++) {
            int idx = tid + it*256;
            int r = idx / 12, c4 = (idx % 12) * 4;
            float4 kv = *(const float4*)(kp + (size_t)(k0 + r)*HD + c4);
            float* dk = Ks + r*QPAD + c4;
            dk[0]=kv.x; dk[1]=kv.y; dk[2]=kv.z; dk[3]=kv.w;
            float4 vv = *(const float4*)(vp + (size_t)(k0 + r)*HD + c4);
            float* dv = Vs + r*QPAD + c4;
            dv[0]=vv.x; dv[1]=vv.y; dv[2]=vv.z; dv[3]=vv.w;
        }
        if (tid < 64) km[tid] = mask[b*NSEQ + k0 + tid];
        __syncthreads();

        /* S = Q K^T (64x64) */
        float s[4][4];
        #pragma unroll
        for (int i = 0; i < 4; i++)
            #pragma unroll
            for (int j = 0; j < 4; j++) s[i][j] = 0.f;
        #pragma unroll 4
        for (int k = 0; k < HD; k++) {
            float a0 = Qs[(ty4+0)*QPAD + k];
            float a1 = Qs[(ty4+1)*QPAD + k];
            float a2 = Qs[(ty4+2)*QPAD + k];
            float a3 = Qs[(ty4+3)*QPAD + k];
            float b0 = Ks[(tx4+0)*QPAD + k];
            float b1 = Ks[(tx4+1)*QPAD + k];
            float b2 = Ks[(tx4+2)*QPAD + k];
            float b3 = Ks[(tx4+3)*QPAD + k];
            s[0][0]+=a0*b0; s[0][1]+=a0*b1; s[0][2]+=a0*b2; s[0][3]+=a0*b3;
            s[1][0]+=a1*b0; s[1][1]+=a1*b1; s[1][2]+=a1*b2; s[1][3]+=a1*b3;
            s[2][0]+=a2*b0; s[2][1]+=a2*b1; s[2][2]+=a2*b2; s[2][3]+=a2*b3;
            s[3][0]+=a3*b0; s[3][1]+=a3*b1; s[3][2]+=a3*b2; s[3][3]+=a3*b3;
        }
        #pragma unroll
        for (int i = 0; i < 4; i++)
            #pragma unroll
            for (int j = 0; j < 4; j++)
                Ss[(ty4+i)*SPAD + tx4+j] = km[tx4+j] ? s[i][j]*scale : -1e30f;
        __syncthreads();

        /* online softmax: thread tid<64 owns one row */
        if (tid < 64) {
            float* srow = Ss + tid*SPAD;
            float mo = rowm[tid];
            float mn = mo;
            #pragma unroll 8
            for (int j = 0; j < 64; j++) mn = fmaxf(mn, srow[j]);
            float f = __expf(mo - mn);         /* exp(-inf)=0 first tile */
            float l = rowl[tid] * f;
            #pragma unroll 8
            for (int j = 0; j < 64; j++) {
                float p = __expf(srow[j] - mn);
                srow[j] = p;
                l += p;
            }
            rowm[tid] = mn; rowl[tid] = l; rowf[tid] = f;
        }
        __syncthreads();

        /* rescale accumulators + P@V */
        #pragma unroll
        for (int i = 0; i < 4; i++) {
            float f = rowf[ty4+i];
            acc[i][0]*=f; acc[i][1]*=f; acc[i][2]*=f;
        }
        #pragma unroll 4
        for (int kk = 0; kk < 64; kk++) {
            float p0 = Ss[(ty4+0)*SPAD + kk];
            float p1 = Ss[(ty4+1)*SPAD + kk];
            float p2 = Ss[(ty4+2)*SPAD + kk];
            float p3 = Ss[(ty4+3)*SPAD + kk];
            float v0 = Vs[kk*QPAD + tc3+0];
            float v1 = Vs[kk*QPAD + tc3+1];
            float v2 = Vs[kk*QPAD + tc3+2];
            acc[0][0]+=p0*v0; acc[0][1]+=p0*v1; acc[0][2]+=p0*v2;
            acc[1][0]+=p1*v0; acc[1][1]+=p1*v1; acc[1][2]+=p1*v2;
            acc[2][0]+=p2*v0; acc[2][1]+=p2*v1; acc[2][2]+=p2*v2;
            acc[3][0]+=p3*v0; acc[3][1]+=p3*v1; acc[3][2]+=p3*v2;
        }
    }

    /* epilogue: O[(b,n,h*48+d)] = acc / l */
    #pragma unroll
    for (int i = 0; i < 4; i++) {
        int n = q0 + ty4 + i;
        float inv = 1.0f / rowl[ty4 + i];
        float* op = O + ((size_t)(b*NSEQ + n))*BDIM + h*HD + tc3;
        op[0] = acc[i][0]*inv;
        op[1] = acc[i][1]*inv;
        op[2] = acc[i][2]*inv;
    }
}

/* ------------------------------ launch ------------------------------ */
extern "C" void kernel_launch(void* const* d_in, const int* in_sizes, int n_in,
                              void* d_out, int out_size) {
    const float* x    = (const float*)d_in[0];
    const float* pos  = (const float*)d_in[1];
    const void*  mask = d_in[2];
    const float* Wq   = (const float*)d_in[3];
    const float* bq   = (const float*)d_in[4];
    const float* Wk   = (const float*)d_in[5];
    const float* bk   = (const float*)d_in[6];
    const float* Wv   = (const float*)d_in[7];
    const float* bv   = (const float*)d_in[8];
    const float* pw1  = (const float*)d_in[9];
    const float* pb1  = (const float*)d_in[10];
    const float* pw2  = (const float*)d_in[11];
    const float* pb2  = (const float*)d_in[12];
    const float* Wo   = (const float*)d_in[13];
    const float* bo   = (const float*)d_in[14];
    const float* mw1  = (const float*)d_in[15];
    const float* mb1  = (const float*)d_in[16];
    const float* mw2  = (const float*)d_in[17];
    const float* mb2  = (const float*)d_in[18];
    const float* g1   = (const float*)d_in[19];
    const float* be1  = (const float*)d_in[20];
    const float* g2   = (const float*)d_in[21];
    const float* be2  = (const float*)d_in[22];
    float* out = (float*)d_out;

    void *ph, *pq, *pk, *pv, *ppe, *patt, *px1, *phid, *pm;
    cudaGetSymbolAddress(&ph,  g_h);
    cudaGetSymbolAddress(&pq,  g_q);
    cudaGetSymbolAddress(&pk,  g_k);
    cudaGetSymbolAddress(&pv,  g_v);
    cudaGetSymbolAddress(&ppe, g_pe);
    cudaGetSymbolAddress(&patt,g_att);
    cudaGetSymbolAddress(&px1, g_x1);
    cudaGetSymbolAddress(&phid,g_hid);
    cudaGetSymbolAddress(&pm,  g_mask);
    float* h   = (float*)ph;
    float* q   = (float*)pq;
    float* k   = (float*)pk;
    float* v   = (float*)pv;
    float* pe  = (float*)ppe;
    float* att = (float*)patt;
    float* x1  = (float*)px1;
    float* hid = (float*)phid;
    int*   msk = (int*)pm;

    cudaFuncSetAttribute(attn_kernel,
                         cudaFuncAttributeMaxDynamicSharedMemorySize, ATT_SMEM);

    /* 1. mask */
    mask_convert_kernel<<<1, 256>>>(mask, MROWS, msk);
    /* 2. LN1 */
    ln_kernel<<<MROWS, 128>>>(x, g1, be1, h);
    /* 3. positional MLP */
    pe_kernel<<<MROWS, 64>>>(pos, pw1, pb1, pw2, pb2, pe);
    /* 4. QKV projections (scatter to (B,H,N,48); K adds pe) */
    dim3 gq(MROWS/BM, BDIM/BN);
    gemm_kernel<1><<<gq, 256>>>(h, Wq, bq, q, BDIM, BDIM, pe, nullptr, 0);
    gemm_kernel<1><<<gq, 256>>>(h, Wk, bk, k, BDIM, BDIM, pe, nullptr, 1);
    gemm_kernel<1><<<gq, 256>>>(h, Wv, bv, v, BDIM, BDIM, pe, nullptr, 0);
    /* 5. attention */
    dim3 ga(NSEQ/64, NB*HEADS);
    attn_kernel<<<ga, 256, ATT_SMEM>>>(q, k, v, msk, att);
    /* 6. Wo + mask + residual -> x1 */
    gemm_kernel<2><<<gq, 256>>>(att, Wo, bo, x1, BDIM, BDIM, x, msk, 0);
    /* 7. LN2 */
    ln_kernel<<<MROWS, 128>>>(x1, g2, be2, h);
    /* 8. MLP1 + gelu */
    dim3 gm1(MROWS/BM, MLPH/BN);
    gemm_kernel<3><<<gm1, 256>>>(h, mw1, mb1, hid, BDIM, MLPH, nullptr, nullptr, 0);
    /* 9. MLP2 + residual + mask -> out */
    gemm_kernel<4><<<gq, 256>>>(hid, mw2, mb2, out, MLPH, BDIM, x1, msk, 0);
}

// round 2
// speedup vs baseline: 2.7651x; 2.7651x over previous
#include <cuda_runtime.h>
#include <math.h>
#include <stdint.h>

#define BDIM 384
#define HEADS 8
#define HD 48
#define NSEQ 2048
#define NB 4
#define MROWS (NB*NSEQ)      /* 8192 */
#define MLPH 1536

/* ------------ scratch (device globals; no allocation allowed) ------------ */
__device__ float g_h [MROWS*BDIM];
__device__ float g_q [MROWS*BDIM];
__device__ float g_k [MROWS*BDIM];
__device__ float g_v [MROWS*BDIM];
__device__ float g_pe[MROWS*HD];
__device__ float g_att[MROWS*BDIM];
__device__ float g_x1[MROWS*BDIM];
__device__ float g_hid[MROWS*MLPH];
__device__ int   g_mask[MROWS];

__device__ __forceinline__ float gelu_exact(float x) {
    return 0.5f * x * (1.0f + erff(x * 0.70710678118654752f));
}

__device__ __forceinline__ uint32_t f2tf(float x) {
    uint32_t u;
    asm("cvt.rna.tf32.f32 %0, %1;" : "=r"(u) : "f"(x));
    return u;
}

/* m16n8k8 tf32 mma, fp32 accumulate.
   A frag: a0=(g,t) a1=(g+8,t) a2=(g,t+4) a3=(g+8,t+4); g=lane>>2, t=lane&3
   B frag: b0=(k=t, n=g) b1=(k=t+4, n=g)
   C frag: c0=(g,2t) c1=(g,2t+1) c2=(g+8,2t) c3=(g+8,2t+1)                  */
__device__ __forceinline__ void mma8(float* c,
                                     uint32_t a0, uint32_t a1, uint32_t a2, uint32_t a3,
                                     uint32_t b0, uint32_t b1) {
    asm volatile(
      "mma.sync.aligned.m16n8k8.row.col.f32.tf32.tf32.f32 "
      "{%0,%1,%2,%3},{%4,%5,%6,%7},{%8,%9},{%0,%1,%2,%3};"
      : "+f"(c[0]), "+f"(c[1]), "+f"(c[2]), "+f"(c[3])
      : "r"(a0), "r"(a1), "r"(a2), "r"(a3), "r"(b0), "r"(b1));
}

/* ------------ mask dtype sniffing + conversion ------------ */
__global__ void mask_convert_kernel(const void* __restrict__ mptr, int n,
                                    int* __restrict__ out) {
    const unsigned char* b = (const unsigned char*)mptr;
    __shared__ int f32flag, nm4flag;
    if (threadIdx.x == 0) { f32flag = 0; nm4flag = 0; }
    __syncthreads();
    int lf = 0, ln4 = 0;
    for (int i = threadIdx.x; i < n; i += blockDim.x) {
        unsigned char c = b[i];
        if (c == 0x3Fu && (i & 3) == 3) lf = 1;
        if (c != 0u   && (i & 3) != 0) ln4 = 1;
    }
    if (lf)  atomicOr(&f32flag, 1);
    if (ln4) atomicOr(&nm4flag, 1);
    __syncthreads();
    int mode = f32flag ? 2 : (nm4flag ? 0 : 1);
    for (int i = threadIdx.x; i < n; i += blockDim.x) {
        int v;
        if      (mode == 0) v = (b[i] != 0);
        else if (mode == 1) v = (((const int*)mptr)[i]   != 0);
        else                v = (((const float*)mptr)[i] != 0.0f);
        out[i] = v;
    }
}

/* ------------ LayerNorm over 384 cols ------------ */
__device__ __forceinline__ float warp_sum(float v) {
    #pragma unroll
    for (int o = 16; o; o >>= 1) v += __shfl_xor_sync(0xffffffffu, v, o);
    return v;
}

__global__ void ln_kernel(const float* __restrict__ X,
                          const float* __restrict__ g,
                          const float* __restrict__ be,
                          float* __restrict__ Y) {
    int row = blockIdx.x;
    const float* x = X + (size_t)row * BDIM;
    float*       y = Y + (size_t)row * BDIM;
    int t = threadIdx.x;
    float v0 = x[t], v1 = x[t + 128], v2 = x[t + 256];
    float s  = v0 + v1 + v2;
    float sq = v0*v0 + v1*v1 + v2*v2;
    s = warp_sum(s); sq = warp_sum(sq);
    __shared__ float ss[4], sqq[4];
    int w = t >> 5, lane = t & 31;
    if (lane == 0) { ss[w] = s; sqq[w] = sq; }
    __syncthreads();
    float S  = ss[0] + ss[1] + ss[2] + ss[3];
    float SQ = sqq[0] + sqq[1] + sqq[2] + sqq[3];
    float mean = S * (1.0f / BDIM);
    float var  = SQ * (1.0f / BDIM) - mean * mean;
    float rstd = rsqrtf(var + 1e-5f);
    y[t      ] = (v0 - mean) * rstd * g[t      ] + be[t      ];
    y[t + 128] = (v1 - mean) * rstd * g[t + 128] + be[t + 128];
    y[t + 256] = (v2 - mean) * rstd * g[t + 256] + be[t + 256];
}

/* ------------ positional MLP ------------ */
__global__ void pe_kernel(const float* __restrict__ pos,
                          const float* __restrict__ pw1,
                          const float* __restrict__ pb1,
                          const float* __restrict__ pw2,
                          const float* __restrict__ pb2,
                          float* __restrict__ pe) {
    int row = blockIdx.x;
    __shared__ float t[HD];
    int i = threadIdx.x;
    float p0 = pos[row*3], p1 = pos[row*3+1], p2 = pos[row*3+2];
    if (i < HD) {
        float u = p0*pw1[i] + p1*pw1[HD+i] + p2*pw1[2*HD+i] + pb1[i];
        t[i] = gelu_exact(u);
    }
    __syncthreads();
    if (i < HD) {
        float acc = pb2[i];
        #pragma unroll 8
        for (int k = 0; k < HD; k++) acc += t[k] * pw2[k*HD + i];
        pe[(size_t)row*HD + i] = acc;
    }
}

/* ------------ tf32 tensor-core GEMM, 128x64x32 tiles ------------
   EPI 1: QKV scatter  -> C[((b*8+h)*2048+n)*48+d] = acc+bias (+pe if flag)
   EPI 2: Wo           -> C = (acc+bias)*mask[row] + extra[row,col]
   EPI 3: MLP1         -> C = gelu(acc+bias)
   EPI 4: MLP2         -> C = (acc+bias+extra[row,col])*mask[row]            */
#define GBM 128
#define GBN 64
#define GBK 32
#define APAD 36
#define WPAD 72

template<int EPI>
__global__ __launch_bounds__(256)
void gemm_tc(const float* __restrict__ A, const float* __restrict__ W,
             const float* __restrict__ bias, float* __restrict__ C,
             int K, int Nc,
             const float* __restrict__ extra, const int* __restrict__ mask,
             int flag) {
    __shared__ uint32_t As[GBM*APAD];
    __shared__ uint32_t Ws[GBK*WPAD];
    int tid = threadIdx.x, lane = tid & 31, w = tid >> 5;
    int g = lane >> 2, t = lane & 3;
    int wm = w >> 1, wn = w & 1;
    int bm = blockIdx.x * GBM, bn = blockIdx.y * GBN;

    float acc[2][4][4];
    #pragma unroll
    for (int mi = 0; mi < 2; mi++)
        #pragma unroll
        for (int nj = 0; nj < 4; nj++)
            #pragma unroll
            for (int r = 0; r < 4; r++) acc[mi][nj][r] = 0.f;

    for (int k0 = 0; k0 < K; k0 += GBK) {
        float4 av[4], wv[2];
        #pragma unroll
        for (int i = 0; i < 4; i++) {
            int idx = tid + i*256;
            int r = idx >> 3, kq = idx & 7;
            av[i] = *(const float4*)(A + (size_t)(bm + r)*K + k0 + kq*4);
        }
        #pragma unroll
        for (int i = 0; i < 2; i++) {
            int idx = tid + i*256;
            int r = idx >> 4, nq = idx & 15;
            wv[i] = *(const float4*)(W + (size_t)(k0 + r)*Nc + bn + nq*4);
        }
        __syncthreads();
        #pragma unroll
        for (int i = 0; i < 4; i++) {
            int idx = tid + i*256;
            int r = idx >> 3, kq = idx & 7;
            uint32_t* d = As + r*APAD + kq*4;
            d[0]=f2tf(av[i].x); d[1]=f2tf(av[i].y); d[2]=f2tf(av[i].z); d[3]=f2tf(av[i].w);
        }
        #pragma unroll
        for (int i = 0; i < 2; i++) {
            int idx = tid + i*256;
            int r = idx >> 4, nq = idx & 15;
            uint32_t* d = Ws + r*WPAD + nq*4;
            d[0]=f2tf(wv[i].x); d[1]=f2tf(wv[i].y); d[2]=f2tf(wv[i].z); d[3]=f2tf(wv[i].w);
        }
        __syncthreads();

        #pragma unroll
        for (int ks = 0; ks < 4; ks++) {
            int kb = ks*8;
            uint32_t af[2][4];
            #pragma unroll
            for (int mi = 0; mi < 2; mi++) {
                int rb = wm*32 + mi*16 + g;
                af[mi][0] = As[rb*APAD + kb + t];
                af[mi][1] = As[(rb+8)*APAD + kb + t];
                af[mi][2] = As[rb*APAD + kb + t + 4];
                af[mi][3] = As[(rb+8)*APAD + kb + t + 4];
            }
            #pragma unroll
            for (int nj = 0; nj < 4; nj++) {
                int nb = wn*32 + nj*8 + g;
                uint32_t b0 = Ws[(kb+t)*WPAD + nb];
                uint32_t b1 = Ws[(kb+t+4)*WPAD + nb];
                mma8(acc[0][nj], af[0][0], af[0][1], af[0][2], af[0][3], b0, b1);
                mma8(acc[1][nj], af[1][0], af[1][1], af[1][2], af[1][3], b0, b1);
            }
        }
        __syncthreads();
    }

    /* epilogue: c0,c1 at (row, 2t / 2t+1); c2,c3 at (row+8, ...) */
    #pragma unroll
    for (int mi = 0; mi < 2; mi++) {
        #pragma unroll
        for (int half = 0; half < 2; half++) {
            int row = bm + wm*32 + mi*16 + g + half*8;
            #pragma unroll
            for (int nj = 0; nj < 4; nj++) {
                int col = bn + wn*32 + nj*8 + 2*t;
                float v0 = acc[mi][nj][half*2+0] + bias[col];
                float v1 = acc[mi][nj][half*2+1] + bias[col+1];
                if (EPI == 1) {
                    int d = col % HD, hh = col / HD;
                    if (flag) {
                        v0 += extra[(size_t)row*HD + d];
                        v1 += extra[(size_t)row*HD + d + 1];
                    }
                    int bb = row >> 11, n = row & (NSEQ-1);
                    float* p = C + (((size_t)(bb*HEADS + hh))*NSEQ + n)*HD + d;
                    p[0] = v0; p[1] = v1;
                } else if (EPI == 2) {
                    float m = (float)mask[row];
                    v0 = v0*m + extra[(size_t)row*Nc + col];
                    v1 = v1*m + extra[(size_t)row*Nc + col + 1];
                    float* p = C + (size_t)row*Nc + col;
                    p[0] = v0; p[1] = v1;
                } else if (EPI == 3) {
                    float* p = C + (size_t)row*Nc + col;
                    p[0] = gelu_exact(v0); p[1] = gelu_exact(v1);
                } else {
                    float m = (float)mask[row];
                    v0 = (v0 + extra[(size_t)row*Nc + col])*m;
                    v1 = (v1 + extra[(size_t)row*Nc + col + 1])*m;
                    float* p = C + (size_t)row*Nc + col;
                    p[0] = v0; p[1] = v1;
                }
            }
        }
    }
}

/* ------------ flash attention with tf32 mma ------------
   block = 64 q-rows x one (b,h); 8 warps: wm=w>>1 (16 rows each), wn=w&1.
   S:  warp tile 16x32 (4 n-atoms), k=48 (6 k-steps), Q frags in registers.
   PV: warp tile 16x24 (3 n-atoms), k=64 (8 k-steps), P via smem (tf32).   */
#define KS_STRIDE 52
#define VS_STRIDE 56
#define SS_STRIDE 68
#define ATT_SMEM ((64*KS_STRIDE + 64*VS_STRIDE + 64*SS_STRIDE)*4 + 64*4*4)

__global__ __launch_bounds__(256)
void attn_tc(const float* __restrict__ Q, const float* __restrict__ Kb,
             const float* __restrict__ Vb, const int* __restrict__ mask,
             float* __restrict__ O) {
    extern __shared__ uint32_t sm[];
    uint32_t* Ks = sm;                          /* [64][52] tf32 */
    uint32_t* Vs = Ks + 64*KS_STRIDE;           /* [64][56] tf32 */
    uint32_t* Ss = Vs + 64*VS_STRIDE;           /* [64][68] f32 S then tf32 P */
    float*    Ssf = (float*)Ss;
    float* rowm = (float*)(Ss + 64*SS_STRIDE);
    float* rowl = rowm + 64;
    float* rowf = rowl + 64;
    int*   km   = (int*)(rowf + 64);

    int bh = blockIdx.y, b = bh >> 3, h = bh & 7;
    int q0 = blockIdx.x * 64;
    int tid = threadIdx.x, lane = tid & 31, w = tid >> 5;
    int g = lane >> 2, t = lane & 3;
    int wm = w >> 1, wn = w & 1;
    const float* qp = Q  + (size_t)bh * NSEQ * HD;
    const float* kp = Kb + (size_t)bh * NSEQ * HD;
    const float* vp = Vb + (size_t)bh * NSEQ * HD;
    const int*   mp = mask + b * NSEQ;

    /* stage Q (tf32) into Ss region, then pull fragments to registers */
    #pragma unroll
    for (int i = 0; i < 3; i++) {
        int idx = tid + i*256;
        int r = idx / 12, c4 = (idx % 12) * 4;
        float4 qv = *(const float4*)(qp + (size_t)(q0 + r)*HD + c4);
        uint32_t* d = Ss + r*KS_STRIDE + c4;
        d[0]=f2tf(qv.x); d[1]=f2tf(qv.y); d[2]=f2tf(qv.z); d[3]=f2tf(qv.w);
    }
    if (tid < 64) { rowm[tid] = -INFINITY; rowl[tid] = 0.f; }
    __syncthreads();
    uint32_t qf[6][4];
    {
        int rq = wm*16 + g;
        #pragma unroll
        for (int ks = 0; ks < 6; ks++) {
            int kb = ks*8;
            qf[ks][0] = Ss[rq*KS_STRIDE + kb + t];
            qf[ks][1] = Ss[(rq+8)*KS_STRIDE + kb + t];
            qf[ks][2] = Ss[rq*KS_STRIDE + kb + t + 4];
            qf[ks][3] = Ss[(rq+8)*KS_STRIDE + kb + t + 4];
        }
    }

    float o[3][4];
    #pragma unroll
    for (int nj = 0; nj < 3; nj++)
        #pragma unroll
        for (int r = 0; r < 4; r++) o[nj][r] = 0.f;
    const float scale = 0.14433756729740643f;   /* 48^-0.5 */

    for (int kt = 0; kt < NSEQ/64; kt++) {
        int k0 = kt * 64;
        __syncthreads();   /* Q-frag extraction / previous PV done */
        #pragma unroll
        for (int i = 0; i < 3; i++) {
            int idx = tid + i*256;
            int r = idx / 12, c4 = (idx % 12) * 4;
            float4 kv = *(const float4*)(kp + (size_t)(k0 + r)*HD + c4);
            uint32_t* dk = Ks + r*KS_STRIDE + c4;
            dk[0]=f2tf(kv.x); dk[1]=f2tf(kv.y); dk[2]=f2tf(kv.z); dk[3]=f2tf(kv.w);
            float4 vv = *(const float4*)(vp + (size_t)(k0 + r)*HD + c4);
            uint32_t* dv = Vs + r*VS_STRIDE + c4;
            dv[0]=f2tf(vv.x); dv[1]=f2tf(vv.y); dv[2]=f2tf(vv.z); dv[3]=f2tf(vv.w);
        }
        if (tid < 64) km[tid] = mp[k0 + tid];
        __syncthreads();

        /* S = Q K^T */
        float s[4][4];
        #pragma unroll
        for (int nj = 0; nj < 4; nj++)
            #pragma unroll
            for (int r = 0; r < 4; r++) s[nj][r] = 0.f;
        #pragma unroll
        for (int ks = 0; ks < 6; ks++) {
            int kb = ks*8;
            #pragma unroll
            for (int nj = 0; nj < 4; nj++) {
                int nb = wn*32 + nj*8 + g;
                uint32_t b0 = Ks[nb*KS_STRIDE + kb + t];
                uint32_t b1 = Ks[nb*KS_STRIDE + kb + t + 4];
                mma8(s[nj], qf[ks][0], qf[ks][1], qf[ks][2], qf[ks][3], b0, b1);
            }
        }
        /* scaled + key-masked S into smem (f32) */
        {
            int r0 = wm*16 + g;
            #pragma unroll
            for (int nj = 0; nj < 4; nj++) {
                int cb = wn*32 + nj*8 + 2*t;
                int m0 = km[cb], m1 = km[cb+1];
                Ssf[r0*SS_STRIDE + cb]       = m0 ? s[nj][0]*scale : -1e30f;
                Ssf[r0*SS_STRIDE + cb + 1]   = m1 ? s[nj][1]*scale : -1e30f;
                Ssf[(r0+8)*SS_STRIDE + cb]   = m0 ? s[nj][2]*scale : -1e30f;
                Ssf[(r0+8)*SS_STRIDE + cb+1] = m1 ? s[nj][3]*scale : -1e30f;
            }
        }
        __syncthreads();

        /* online softmax: 4 threads per row, 16 cols each */
        {
            int r = tid >> 2, c0 = (tid & 3) * 16;
            float v[16];
            float mx = -INFINITY;
            #pragma unroll
            for (int i = 0; i < 16; i++) {
                v[i] = Ssf[r*SS_STRIDE + c0 + i];
                mx = fmaxf(mx, v[i]);
            }
            mx = fmaxf(mx, __shfl_xor_sync(0xffffffffu, mx, 1));
            mx = fmaxf(mx, __shfl_xor_sync(0xffffffffu, mx, 2));
            float mo = rowm[r];
            float mn = fmaxf(mo, mx);
            float f  = __expf(mo - mn);
            float l = 0.f;
            #pragma unroll
            for (int i = 0; i < 16; i++) {
                float p = __expf(v[i] - mn);
                Ss[r*SS_STRIDE + c0 + i] = f2tf(p);
                l += p;
            }
            l += __shfl_xor_sync(0xffffffffu, l, 1);
            l += __shfl_xor_sync(0xffffffffu, l, 2);
            if ((tid & 3) == 0) {
                rowm[r] = mn;
                rowl[r] = rowl[r]*f + l;
                rowf[r] = f;
            }
        }
        __syncthreads();

        /* rescale + P V */
        {
            float f0 = rowf[wm*16 + g], f1 = rowf[wm*16 + g + 8];
            #pragma unroll
            for (int nj = 0; nj < 3; nj++) {
                o[nj][0] *= f0; o[nj][1] *= f0;
                o[nj][2] *= f1; o[nj][3] *= f1;
            }
            int r0 = wm*16 + g;
            #pragma unroll
            for (int ks = 0; ks < 8; ks++) {
                int kb = ks*8;
                uint32_t a0 = Ss[r0*SS_STRIDE + kb + t];
                uint32_t a1 = Ss[(r0+8)*SS_STRIDE + kb + t];
                uint32_t a2 = Ss[r0*SS_STRIDE + kb + t + 4];
                uint32_t a3 = Ss[(r0+8)*SS_STRIDE + kb + t + 4];
                #pragma unroll
                for (int nj = 0; nj < 3; nj++) {
                    int nb = wn*24 + nj*8 + g;
                    uint32_t b0 = Vs[(kb+t)*VS_STRIDE + nb];
                    uint32_t b1 = Vs[(kb+t+4)*VS_STRIDE + nb];
                    mma8(o[nj], a0, a1, a2, a3, b0, b1);
                }
            }
        }
    }

    /* epilogue: divide by l, write to att layout (row-major [8192][384]) */
    {
        int r0 = wm*16 + g;
        float inv0 = 1.0f / rowl[r0];
        float inv1 = 1.0f / rowl[r0 + 8];
        #pragma unroll
        for (int nj = 0; nj < 3; nj++) {
            int cb = wn*24 + nj*8 + 2*t;
            float2 p0 = make_float2(o[nj][0]*inv0, o[nj][1]*inv0);
            float2 p1 = make_float2(o[nj][2]*inv1, o[nj][3]*inv1);
            *(float2*)(O + ((size_t)(b*NSEQ + q0 + r0))*BDIM + h*HD + cb)     = p0;
            *(float2*)(O + ((size_t)(b*NSEQ + q0 + r0 + 8))*BDIM + h*HD + cb) = p1;
        }
    }
}

/* ------------------------------ launch ------------------------------ */
extern "C" void kernel_launch(void* const* d_in, const int* in_sizes, int n_in,
                              void* d_out, int out_size) {
    const float* x    = (const float*)d_in[0];
    const float* pos  = (const float*)d_in[1];
    const void*  mask = d_in[2];
    const float* Wq   = (const float*)d_in[3];
    const float* bq   = (const float*)d_in[4];
    const float* Wk   = (const float*)d_in[5];
    const float* bk   = (const float*)d_in[6];
    const float* Wv   = (const float*)d_in[7];
    const float* bv   = (const float*)d_in[8];
    const float* pw1  = (const float*)d_in[9];
    const float* pb1  = (const float*)d_in[10];
    const float* pw2  = (const float*)d_in[11];
    const float* pb2  = (const float*)d_in[12];
    const float* Wo   = (const float*)d_in[13];
    const float* bo   = (const float*)d_in[14];
    const float* mw1  = (const float*)d_in[15];
    const float* mb1  = (const float*)d_in[16];
    const float* mw2  = (const float*)d_in[17];
    const float* mb2  = (const float*)d_in[18];
    const float* g1   = (const float*)d_in[19];
    const float* be1  = (const float*)d_in[20];
    const float* g2   = (const float*)d_in[21];
    const float* be2  = (const float*)d_in[22];
    float* out = (float*)d_out;

    void *ph, *pq, *pk, *pv, *ppe, *patt, *px1, *phid, *pm;
    cudaGetSymbolAddress(&ph,  g_h);
    cudaGetSymbolAddress(&pq,  g_q);
    cudaGetSymbolAddress(&pk,  g_k);
    cudaGetSymbolAddress(&pv,  g_v);
    cudaGetSymbolAddress(&ppe, g_pe);
    cudaGetSymbolAddress(&patt,g_att);
    cudaGetSymbolAddress(&px1, g_x1);
    cudaGetSymbolAddress(&phid,g_hid);
    cudaGetSymbolAddress(&pm,  g_mask);
    float* h   = (float*)ph;
    float* q   = (float*)pq;
    float* k   = (float*)pk;
    float* v   = (float*)pv;
    float* pe  = (float*)ppe;
    float* att = (float*)patt;
    float* x1  = (float*)px1;
    float* hid = (float*)phid;
    int*   msk = (int*)pm;

    /* 1. mask */
    mask_convert_kernel<<<1, 256>>>(mask, MROWS, msk);
    /* 2. LN1 */
    ln_kernel<<<MROWS, 128>>>(x, g1, be1, h);
    /* 3. positional MLP */
    pe_kernel<<<MROWS, 64>>>(pos, pw1, pb1, pw2, pb2, pe);
    /* 4. QKV projections (scatter to (B,H,N,48); K adds pe) */
    dim3 gq(MROWS/GBM, BDIM/GBN);
    gemm_tc<1><<<gq, 256>>>(h, Wq, bq, q, BDIM, BDIM, pe, nullptr, 0);
    gemm_tc<1><<<gq, 256>>>(h, Wk, bk, k, BDIM, BDIM, pe, nullptr, 1);
    gemm_tc<1><<<gq, 256>>>(h, Wv, bv, v, BDIM, BDIM, pe, nullptr, 0);
    /* 5. attention */
    dim3 ga(NSEQ/64, NB*HEADS);
    attn_tc<<<ga, 256, ATT_SMEM>>>(q, k, v, msk, att);
    /* 6. Wo + mask + residual -> x1 */
    gemm_tc<2><<<gq, 256>>>(att, Wo, bo, x1, BDIM, BDIM, x, msk, 0);
    /* 7. LN2 */
    ln_kernel<<<MROWS, 128>>>(x1, g2, be2, h);
    /* 8. MLP1 + gelu */
    dim3 gm1(MROWS/GBM, MLPH/GBN);
    gemm_tc<3><<<gm1, 256>>>(h, mw1, mb1, hid, BDIM, MLPH, nullptr, nullptr, 0);
    /* 9. MLP2 + residual + mask -> out */
    gemm_tc<4><<<gq, 256>>>(hid, mw2, mb2, out, MLPH, BDIM, x1, msk, 0);
}

// round 3
// speedup vs baseline: 3.4435x; 1.2453x over previous
#include <cuda_runtime.h>
#include <math.h>
#include <stdint.h>

#define BDIM 384
#define HEADS 8
#define HD 48
#define NSEQ 2048
#define NB 4
#define MROWS (NB*NSEQ)      /* 8192 */
#define MLPH 1536
#define QKVN (3*BDIM)        /* 1152 */

/* ------------ scratch (device globals; no allocation allowed) ------------ */
__device__ float g_h [MROWS*BDIM];
__device__ float g_q [MROWS*BDIM];
__device__ float g_k [MROWS*BDIM];
__device__ float g_v [MROWS*BDIM];
__device__ float g_pe[MROWS*HD];
__device__ float g_att[MROWS*BDIM];
__device__ float g_x1[MROWS*BDIM];
__device__ float g_hid[MROWS*MLPH];
__device__ int   g_mask[MROWS];
__device__ float g_mb [MROWS];          /* 0 or -1e30 mask bias */
__device__ float g_wqkv[BDIM*QKVN];
__device__ float g_bqkv[QKVN];

__device__ __forceinline__ float gelu_exact(float x) {
    return 0.5f * x * (1.0f + erff(x * 0.70710678118654752f));
}

/* m16n8k8 tf32 mma, fp32 accumulate. Raw f32 bits fed as tf32 (HW truncates). */
__device__ __forceinline__ void mma8(float* c,
                                     uint32_t a0, uint32_t a1, uint32_t a2, uint32_t a3,
                                     uint32_t b0, uint32_t b1) {
    asm volatile(
      "mma.sync.aligned.m16n8k8.row.col.f32.tf32.tf32.f32 "
      "{%0,%1,%2,%3},{%4,%5,%6,%7},{%8,%9},{%0,%1,%2,%3};"
      : "+f"(c[0]), "+f"(c[1]), "+f"(c[2]), "+f"(c[3])
      : "r"(a0), "r"(a1), "r"(a2), "r"(a3), "r"(b0), "r"(b1));
}

__device__ __forceinline__ void cpa16(void* dst, const void* src) {
    uint32_t d = (uint32_t)__cvta_generic_to_shared(dst);
    asm volatile("cp.async.ca.shared.global [%0], [%1], 16;" :: "r"(d), "l"(src));
}
__device__ __forceinline__ void cpa4(void* dst, const void* src) {
    uint32_t d = (uint32_t)__cvta_generic_to_shared(dst);
    asm volatile("cp.async.ca.shared.global [%0], [%1], 4;" :: "r"(d), "l"(src));
}
#define CP_COMMIT() asm volatile("cp.async.commit_group;")
template<int N> __device__ __forceinline__ void cp_wait() {
    asm volatile("cp.async.wait_group %0;" :: "n"(N));
}

/* ------------ mask dtype sniffing + conversion (+ float bias) ------------ */
__global__ void mask_convert_kernel(const void* __restrict__ mptr, int n,
                                    int* __restrict__ out, float* __restrict__ fb) {
    const unsigned char* b = (const unsigned char*)mptr;
    __shared__ int f32flag, nm4flag;
    if (threadIdx.x == 0) { f32flag = 0; nm4flag = 0; }
    __syncthreads();
    int lf = 0, ln4 = 0;
    for (int i = threadIdx.x; i < n; i += blockDim.x) {
        unsigned char c = b[i];
        if (c == 0x3Fu && (i & 3) == 3) lf = 1;
        if (c != 0u   && (i & 3) != 0) ln4 = 1;
    }
    if (lf)  atomicOr(&f32flag, 1);
    if (ln4) atomicOr(&nm4flag, 1);
    __syncthreads();
    int mode = f32flag ? 2 : (nm4flag ? 0 : 1);
    for (int i = threadIdx.x; i < n; i += blockDim.x) {
        int v;
        if      (mode == 0) v = (b[i] != 0);
        else if (mode == 1) v = (((const int*)mptr)[i]   != 0);
        else                v = (((const float*)mptr)[i] != 0.0f);
        out[i] = v;
        fb[i]  = v ? 0.0f : -1e30f;
    }
}

/* ------------ pack Wq|Wk|Wv -> [384][1152] ------------ */
__global__ void pack_qkv_kernel(const float* __restrict__ Wq, const float* __restrict__ Wk,
                                const float* __restrict__ Wv, const float* __restrict__ bq,
                                const float* __restrict__ bk, const float* __restrict__ bv,
                                float* __restrict__ Wp, float* __restrict__ bp) {
    int idx = blockIdx.x * 256 + threadIdx.x;
    if (idx < BDIM*QKVN) {
        int r = idx / QKVN, c = idx % QKVN;
        int sec = c / BDIM, cc = c % BDIM;
        float v = (sec == 0) ? Wq[r*BDIM+cc] : (sec == 1) ? Wk[r*BDIM+cc] : Wv[r*BDIM+cc];
        Wp[idx] = v;
    }
    if (idx < QKVN) {
        int sec = idx / BDIM, cc = idx % BDIM;
        bp[idx] = (sec == 0) ? bq[cc] : (sec == 1) ? bk[cc] : bv[cc];
    }
}

/* ------------ LayerNorm over 384 cols ------------ */
__device__ __forceinline__ float warp_sum(float v) {
    #pragma unroll
    for (int o = 16; o; o >>= 1) v += __shfl_xor_sync(0xffffffffu, v, o);
    return v;
}

__global__ void ln_kernel(const float* __restrict__ X,
                          const float* __restrict__ g,
                          const float* __restrict__ be,
                          float* __restrict__ Y) {
    int row = blockIdx.x;
    const float* x = X + (size_t)row * BDIM;
    float*       y = Y + (size_t)row * BDIM;
    int t = threadIdx.x;
    float v0 = x[t], v1 = x[t + 128], v2 = x[t + 256];
    float s  = v0 + v1 + v2;
    float sq = v0*v0 + v1*v1 + v2*v2;
    s = warp_sum(s); sq = warp_sum(sq);
    __shared__ float ss[4], sqq[4];
    int w = t >> 5, lane = t & 31;
    if (lane == 0) { ss[w] = s; sqq[w] = sq; }
    __syncthreads();
    float S  = ss[0] + ss[1] + ss[2] + ss[3];
    float SQ = sqq[0] + sqq[1] + sqq[2] + sqq[3];
    float mean = S * (1.0f / BDIM);
    float var  = SQ * (1.0f / BDIM) - mean * mean;
    float rstd = rsqrtf(var + 1e-5f);
    y[t      ] = (v0 - mean) * rstd * g[t      ] + be[t      ];
    y[t + 128] = (v1 - mean) * rstd * g[t + 128] + be[t + 128];
    y[t + 256] = (v2 - mean) * rstd * g[t + 256] + be[t + 256];
}

/* ------------ positional MLP ------------ */
__global__ void pe_kernel(const float* __restrict__ pos,
                          const float* __restrict__ pw1,
                          const float* __restrict__ pb1,
                          const float* __restrict__ pw2,
                          const float* __restrict__ pb2,
                          float* __restrict__ pe) {
    int row = blockIdx.x;
    __shared__ float t[HD];
    int i = threadIdx.x;
    float p0 = pos[row*3], p1 = pos[row*3+1], p2 = pos[row*3+2];
    if (i < HD) {
        float u = p0*pw1[i] + p1*pw1[HD+i] + p2*pw1[2*HD+i] + pb1[i];
        t[i] = gelu_exact(u);
    }
    __syncthreads();
    if (i < HD) {
        float acc = pb2[i];
        #pragma unroll 8
        for (int k = 0; k < HD; k++) acc += t[k] * pw2[k*HD + i];
        pe[(size_t)row*HD + i] = acc;
    }
}

/* ------------ tf32 tensor-core GEMM, 128x64x32, cp.async 2-stage ------------
   EPI 1: fused QKV scatter -> q/k/v[(b,h,n,d)] = acc+bias (+pe for K section)
   EPI 2: Wo           -> C = (acc+bias)*mask[row] + extra[row,col]
   EPI 3: MLP1         -> C = gelu(acc+bias)
   EPI 4: MLP2         -> C = (acc+bias+extra[row,col])*mask[row]            */
#define GBM 128
#define GBN 64
#define GBK 32
#define APAD 36
#define WPAD 72

template<int EPI>
__global__ __launch_bounds__(256)
void gemm_tc(const float* __restrict__ A, const float* __restrict__ W,
             const float* __restrict__ bias, float* __restrict__ C,
             int K, int Nc,
             const float* __restrict__ extra, const int* __restrict__ mask,
             float* __restrict__ Ck, float* __restrict__ Cv) {
    __shared__ float As[2][GBM*APAD];
    __shared__ float Ws[2][GBK*WPAD];
    int tid = threadIdx.x, lane = tid & 31, w = tid >> 5;
    int g = lane >> 2, t = lane & 3;
    int wm = w >> 1, wn = w & 1;
    int bm = blockIdx.x * GBM, bn = blockIdx.y * GBN;

    float acc[2][4][4];
    #pragma unroll
    for (int mi = 0; mi < 2; mi++)
        #pragma unroll
        for (int nj = 0; nj < 4; nj++)
            #pragma unroll
            for (int r = 0; r < 4; r++) acc[mi][nj][r] = 0.f;

    int a_r = tid >> 3, a_c = (tid & 7) * 4;       /* rows 0..31 (+32i), cols */
    int w_r = tid >> 4, w_c = (tid & 15) * 4;      /* rows 0..15 (+16i) */

    /* prologue: stage 0 */
    {
        #pragma unroll
        for (int i = 0; i < 4; i++)
            cpa16(&As[0][(a_r + i*32)*APAD + a_c],
                  A + (size_t)(bm + a_r + i*32)*K + a_c);
        #pragma unroll
        for (int i = 0; i < 2; i++)
            cpa16(&Ws[0][(w_r + i*16)*WPAD + w_c],
                  W + (size_t)(w_r + i*16)*Nc + bn + w_c);
        CP_COMMIT();
    }

    int ntiles = K / GBK;
    for (int kt = 0; kt < ntiles; kt++) {
        __syncthreads();                   /* next stage buf free of readers */
        if (kt + 1 < ntiles) {
            int k0 = (kt + 1) * GBK, st = (kt + 1) & 1;
            #pragma unroll
            for (int i = 0; i < 4; i++)
                cpa16(&As[st][(a_r + i*32)*APAD + a_c],
                      A + (size_t)(bm + a_r + i*32)*K + k0 + a_c);
            #pragma unroll
            for (int i = 0; i < 2; i++)
                cpa16(&Ws[st][(w_r + i*16)*WPAD + w_c],
                      W + (size_t)(k0 + w_r + i*16)*Nc + bn + w_c);
            CP_COMMIT();
            cp_wait<1>();
        } else {
            cp_wait<0>();
        }
        __syncthreads();
        const float* as = As[kt & 1];
        const float* ws = Ws[kt & 1];

        #pragma unroll
        for (int ks = 0; ks < 4; ks++) {
            int kb = ks*8;
            uint32_t af[2][4];
            #pragma unroll
            for (int mi = 0; mi < 2; mi++) {
                int rb = wm*32 + mi*16 + g;
                af[mi][0] = __float_as_uint(as[rb*APAD + kb + t]);
                af[mi][1] = __float_as_uint(as[(rb+8)*APAD + kb + t]);
                af[mi][2] = __float_as_uint(as[rb*APAD + kb + t + 4]);
                af[mi][3] = __float_as_uint(as[(rb+8)*APAD + kb + t + 4]);
            }
            #pragma unroll
            for (int nj = 0; nj < 4; nj++) {
                int nb = wn*32 + nj*8 + g;
                uint32_t b0 = __float_as_uint(ws[(kb+t)*WPAD + nb]);
                uint32_t b1 = __float_as_uint(ws[(kb+t+4)*WPAD + nb]);
                mma8(acc[0][nj], af[0][0], af[0][1], af[0][2], af[0][3], b0, b1);
                mma8(acc[1][nj], af[1][0], af[1][1], af[1][2], af[1][3], b0, b1);
            }
        }
    }

    #pragma unroll
    for (int mi = 0; mi < 2; mi++) {
        #pragma unroll
        for (int half = 0; half < 2; half++) {
            int row = bm + wm*32 + mi*16 + g + half*8;
            #pragma unroll
            for (int nj = 0; nj < 4; nj++) {
                int col = bn + wn*32 + nj*8 + 2*t;
                float v0 = acc[mi][nj][half*2+0] + bias[col];
                float v1 = acc[mi][nj][half*2+1] + bias[col+1];
                if (EPI == 1) {
                    int sec = col / BDIM;
                    int c2  = col - sec*BDIM;
                    int d = c2 % HD, hh = c2 / HD;
                    if (sec == 1) {
                        v0 += extra[(size_t)row*HD + d];
                        v1 += extra[(size_t)row*HD + d + 1];
                    }
                    int bb = row >> 11, n = row & (NSEQ-1);
                    float* base = (sec == 0) ? C : (sec == 1) ? Ck : Cv;
                    float* p = base + (((size_t)(bb*HEADS + hh))*NSEQ + n)*HD + d;
                    p[0] = v0; p[1] = v1;
                } else if (EPI == 2) {
                    float m = (float)mask[row];
                    v0 = v0*m + extra[(size_t)row*Nc + col];
                    v1 = v1*m + extra[(size_t)row*Nc + col + 1];
                    float* p = C + (size_t)row*Nc + col;
                    p[0] = v0; p[1] = v1;
                } else if (EPI == 3) {
                    float* p = C + (size_t)row*Nc + col;
                    p[0] = gelu_exact(v0); p[1] = gelu_exact(v1);
                } else {
                    float m = (float)mask[row];
                    v0 = (v0 + extra[(size_t)row*Nc + col])*m;
                    v1 = (v1 + extra[(size_t)row*Nc + col + 1])*m;
                    float* p = C + (size_t)row*Nc + col;
                    p[0] = v0; p[1] = v1;
                }
            }
        }
    }
}

/* ------------ flash attention: 128 q-rows/block, warp-owned rows ------------
   8 warps x 16 rows; 64-key tiles, cp.async double-buffered K/V/maskbias;
   softmax fully in registers (quad shuffles); P in warp-private smem.       */
#define KPAD 52
#define VPAD 56
#define PPAD 68
#define BQ 128
#define NT (NSEQ/64)
#define ATT_F_KS 0
#define ATT_F_VS (2*64*KPAD)                      /* 6656 */
#define ATT_F_MB (ATT_F_VS + 2*64*VPAD)           /* 13824 */
#define ATT_F_PS (ATT_F_MB + 2*64)                /* 13952 */
#define ATT_SMEM ((ATT_F_PS + 8*16*PPAD) * 4)     /* 90624 B */

__global__ __launch_bounds__(256, 2)
void attn_tc(const float* __restrict__ Q, const float* __restrict__ Kb,
             const float* __restrict__ Vb, const float* __restrict__ mb,
             float* __restrict__ O) {
    extern __shared__ float sm[];
    float* Ks  = sm + ATT_F_KS;
    float* Vs  = sm + ATT_F_VS;
    float* MBs = sm + ATT_F_MB;
    float* Ps  = sm + ATT_F_PS;

    int bh = blockIdx.y, b = bh >> 3, h = bh & 7;
    int q0 = blockIdx.x * BQ;
    int tid = threadIdx.x, lane = tid & 31, w = tid >> 5;
    int g = lane >> 2, t = lane & 3;
    const float* qp = Q  + (size_t)bh * NSEQ * HD;
    const float* kp = Kb + (size_t)bh * NSEQ * HD;
    const float* vp = Vb + (size_t)bh * NSEQ * HD;
    const float* mbp = mb + b * NSEQ;

    /* stage Q (raw f32) into Ps region, extract fragments */
    #pragma unroll
    for (int i = 0; i < 6; i++) {
        int idx = tid + i*256;
        int r = idx / 12, c4 = (idx % 12) * 4;
        *(float4*)(Ps + r*KPAD + c4) = *(const float4*)(qp + (size_t)(q0 + r)*HD + c4);
    }
    __syncthreads();
    uint32_t qf[6][4];
    {
        int rq = w*16 + g;
        #pragma unroll
        for (int ks = 0; ks < 6; ks++) {
            int kb = ks*8;
            qf[ks][0] = __float_as_uint(Ps[rq*KPAD + kb + t]);
            qf[ks][1] = __float_as_uint(Ps[(rq+8)*KPAD + kb + t]);
            qf[ks][2] = __float_as_uint(Ps[rq*KPAD + kb + t + 4]);
            qf[ks][3] = __float_as_uint(Ps[(rq+8)*KPAD + kb + t + 4]);
        }
    }
    __syncthreads();   /* Ps reused for P below */

    float o[6][4];
    #pragma unroll
    for (int nj = 0; nj < 6; nj++)
        #pragma unroll
        for (int r = 0; r < 4; r++) o[nj][r] = 0.f;
    float mA = -INFINITY, mB = -INFINITY, lA = 0.f, lB = 0.f;
    const float scale = 0.14433756729740643f;   /* 48^-0.5 */

    /* prologue: stage 0 */
    {
        #pragma unroll
        for (int i = 0; i < 3; i++) {
            int idx = tid + i*256;
            int r = idx / 12, c4 = (idx % 12) * 4;
            cpa16(Ks + r*KPAD + c4, kp + (size_t)r*HD + c4);
            cpa16(Vs + r*VPAD + c4, vp + (size_t)r*HD + c4);
        }
        if (tid < 64) cpa4(MBs + tid, mbp + tid);
        CP_COMMIT();
    }

    for (int kt = 0; kt < NT; kt++) {
        __syncthreads();                /* next-stage buffers free of readers */
        if (kt + 1 < NT) {
            int st = (kt + 1) & 1, k0 = (kt + 1) * 64;
            #pragma unroll
            for (int i = 0; i < 3; i++) {
                int idx = tid + i*256;
                int r = idx / 12, c4 = (idx % 12) * 4;
                cpa16(Ks + st*64*KPAD + r*KPAD + c4, kp + (size_t)(k0 + r)*HD + c4);
                cpa16(Vs + st*64*VPAD + r*VPAD + c4, vp + (size_t)(k0 + r)*HD + c4);
            }
            if (tid < 64) cpa4(MBs + st*64 + tid, mbp + k0 + tid);
            CP_COMMIT();
            cp_wait<1>();
        } else {
            cp_wait<0>();
        }
        __syncthreads();
        int st = kt & 1;
        const float* Kst  = Ks + st*64*KPAD;
        const float* Vst  = Vs + st*64*VPAD;
        const float* MBst = MBs + st*64;

        /* S = Q K^T : warp tile 16x64 */
        float s[8][4];
        #pragma unroll
        for (int nj = 0; nj < 8; nj++)
            #pragma unroll
            for (int r = 0; r < 4; r++) s[nj][r] = 0.f;
        #pragma unroll
        for (int ks = 0; ks < 6; ks++) {
            int kb = ks*8;
            #pragma unroll
            for (int nj = 0; nj < 8; nj++) {
                int nb = nj*8 + g;
                uint32_t b0 = __float_as_uint(Kst[nb*KPAD + kb + t]);
                uint32_t b1 = __float_as_uint(Kst[nb*KPAD + kb + t + 4]);
                mma8(s[nj], qf[ks][0], qf[ks][1], qf[ks][2], qf[ks][3], b0, b1);
            }
        }

        /* scale + mask bias, row max */
        float mxA = -INFINITY, mxB = -INFINITY;
        #pragma unroll
        for (int nj = 0; nj < 8; nj++) {
            float2 mbv = *(const float2*)(MBst + nj*8 + 2*t);
            s[nj][0] = s[nj][0]*scale + mbv.x;
            s[nj][1] = s[nj][1]*scale + mbv.y;
            s[nj][2] = s[nj][2]*scale + mbv.x;
            s[nj][3] = s[nj][3]*scale + mbv.y;
            mxA = fmaxf(mxA, fmaxf(s[nj][0], s[nj][1]));
            mxB = fmaxf(mxB, fmaxf(s[nj][2], s[nj][3]));
        }
        mxA = fmaxf(mxA, __shfl_xor_sync(0xffffffffu, mxA, 1));
        mxA = fmaxf(mxA, __shfl_xor_sync(0xffffffffu, mxA, 2));
        mxB = fmaxf(mxB, __shfl_xor_sync(0xffffffffu, mxB, 1));
        mxB = fmaxf(mxB, __shfl_xor_sync(0xffffffffu, mxB, 2));

        float mAn = fmaxf(mA, mxA), fA = __expf(mA - mAn);
        float mBn = fmaxf(mB, mxB), fB = __expf(mB - mBn);
        mA = mAn; mB = mBn;
        lA *= fA;  lB *= fB;

        /* P = exp(S - m), write to warp-private smem (raw f32 -> tf32 trunc) */
        float* Pw = Ps + w*16*PPAD;
        #pragma unroll
        for (int nj = 0; nj < 8; nj++) {
            float p0 = __expf(s[nj][0] - mA);
            float p1 = __expf(s[nj][1] - mA);
            float p2 = __expf(s[nj][2] - mB);
            float p3 = __expf(s[nj][3] - mB);
            lA += p0 + p1; lB += p2 + p3;
            *(float2*)(Pw + g*PPAD     + nj*8 + 2*t) = make_float2(p0, p1);
            *(float2*)(Pw + (g+8)*PPAD + nj*8 + 2*t) = make_float2(p2, p3);
        }
        /* rescale output accumulators */
        #pragma unroll
        for (int nj = 0; nj < 6; nj++) {
            o[nj][0] *= fA; o[nj][1] *= fA;
            o[nj][2] *= fB; o[nj][3] *= fB;
        }
        __syncwarp();

        /* O += P V : warp tile 16x48 */
        #pragma unroll
        for (int ks = 0; ks < 8; ks++) {
            int kb = ks*8;
            uint32_t a0 = __float_as_uint(Pw[g*PPAD + kb + t]);
            uint32_t a1 = __float_as_uint(Pw[(g+8)*PPAD + kb + t]);
            uint32_t a2 = __float_as_uint(Pw[g*PPAD + kb + t + 4]);
            uint32_t a3 = __float_as_uint(Pw[(g+8)*PPAD + kb + t + 4]);
            #pragma unroll
            for (int nj = 0; nj < 6; nj++) {
                int nb = nj*8 + g;
                uint32_t b0 = __float_as_uint(Vst[(kb+t)*VPAD + nb]);
                uint32_t b1 = __float_as_uint(Vst[(kb+t+4)*VPAD + nb]);
                mma8(o[nj], a0, a1, a2, a3, b0, b1);
            }
        }
    }

    /* epilogue: reduce l across quad, divide, store */
    lA += __shfl_xor_sync(0xffffffffu, lA, 1);
    lA += __shfl_xor_sync(0xffffffffu, lA, 2);
    lB += __shfl_xor_sync(0xffffffffu, lB, 1);
    lB += __shfl_xor_sync(0xffffffffu, lB, 2);
    float invA = 1.0f / lA, invB = 1.0f / lB;
    int rA = q0 + w*16 + g, rB = rA + 8;
    #pragma unroll
    for (int nj = 0; nj < 6; nj++) {
        int cb = nj*8 + 2*t;
        *(float2*)(O + ((size_t)(b*NSEQ + rA))*BDIM + h*HD + cb) =
            make_float2(o[nj][0]*invA, o[nj][1]*invA);
        *(float2*)(O + ((size_t)(b*NSEQ + rB))*BDIM + h*HD + cb) =
            make_float2(o[nj][2]*invB, o[nj][3]*invB);
    }
}

/* ------------------------------ launch ------------------------------ */
extern "C" void kernel_launch(void* const* d_in, const int* in_sizes, int n_in,
                              void* d_out, int out_size) {
    const float* x    = (const float*)d_in[0];
    const float* pos  = (const float*)d_in[1];
    const void*  mask = d_in[2];
    const float* Wq   = (const float*)d_in[3];
    const float* bq   = (const float*)d_in[4];
    const float* Wk   = (const float*)d_in[5];
    const float* bk   = (const float*)d_in[6];
    const float* Wv   = (const float*)d_in[7];
    const float* bv   = (const float*)d_in[8];
    const float* pw1  = (const float*)d_in[9];
    const float* pb1  = (const float*)d_in[10];
    const float* pw2  = (const float*)d_in[11];
    const float* pb2  = (const float*)d_in[12];
    const float* Wo   = (const float*)d_in[13];
    const float* bo   = (const float*)d_in[14];
    const float* mw1  = (const float*)d_in[15];
    const float* mb1  = (const float*)d_in[16];
    const float* mw2  = (const float*)d_in[17];
    const float* mb2  = (const float*)d_in[18];
    const float* g1   = (const float*)d_in[19];
    const float* be1  = (const float*)d_in[20];
    const float* g2   = (const float*)d_in[21];
    const float* be2  = (const float*)d_in[22];
    float* out = (float*)d_out;

    void *ph, *pq, *pk, *pv, *ppe, *patt, *px1, *phid, *pm, *pmb, *pwq, *pbq;
    cudaGetSymbolAddress(&ph,  g_h);
    cudaGetSymbolAddress(&pq,  g_q);
    cudaGetSymbolAddress(&pk,  g_k);
    cudaGetSymbolAddress(&pv,  g_v);
    cudaGetSymbolAddress(&ppe, g_pe);
    cudaGetSymbolAddress(&patt,g_att);
    cudaGetSymbolAddress(&px1, g_x1);
    cudaGetSymbolAddress(&phid,g_hid);
    cudaGetSymbolAddress(&pm,  g_mask);
    cudaGetSymbolAddress(&pmb, g_mb);
    cudaGetSymbolAddress(&pwq, g_wqkv);
    cudaGetSymbolAddress(&pbq, g_bqkv);
    float* h    = (float*)ph;
    float* q    = (float*)pq;
    float* k    = (float*)pk;
    float* v    = (float*)pv;
    float* pe   = (float*)ppe;
    float* att  = (float*)patt;
    float* x1   = (float*)px1;
    float* hid  = (float*)phid;
    int*   msk  = (int*)pm;
    float* mbf  = (float*)pmb;
    float* wqkv = (float*)pwq;
    float* bqkv = (float*)pbq;

    cudaFuncSetAttribute(attn_tc,
                         cudaFuncAttributeMaxDynamicSharedMemorySize, ATT_SMEM);

    /* 1. mask (+float bias) */
    mask_convert_kernel<<<1, 256>>>(mask, MROWS, msk, mbf);
    /* 2. pack QKV weights */
    pack_qkv_kernel<<<(BDIM*QKVN + 255)/256, 256>>>(Wq, Wk, Wv, bq, bk, bv, wqkv, bqkv);
    /* 3. LN1 */
    ln_kernel<<<MROWS, 128>>>(x, g1, be1, h);
    /* 4. positional MLP */
    pe_kernel<<<MROWS, 64>>>(pos, pw1, pb1, pw2, pb2, pe);
    /* 5. fused QKV projection */
    dim3 gqkv(MROWS/GBM, QKVN/GBN);
    gemm_tc<1><<<gqkv, 256>>>(h, wqkv, bqkv, q, BDIM, QKVN, pe, nullptr, k, v);
    /* 6. attention */
    dim3 ga(NSEQ/BQ, NB*HEADS);
    attn_tc<<<ga, 256, ATT_SMEM>>>(q, k, v, mbf, att);
    /* 7. Wo + mask + residual -> x1 */
    dim3 gwo(MROWS/GBM, BDIM/GBN);
    gemm_tc<2><<<gwo, 256>>>(att, Wo, bo, x1, BDIM, BDIM, x, msk, nullptr, nullptr);
    /* 8. LN2 */
    ln_kernel<<<MROWS, 128>>>(x1, g2, be2, h);
    /* 9. MLP1 + gelu */
    dim3 gm1(MROWS/GBM, MLPH/GBN);
    gemm_tc<3><<<gm1, 256>>>(h, mw1, mb1, hid, BDIM, MLPH, nullptr, nullptr, nullptr, nullptr);
    /* 10. MLP2 + residual + mask -> out */
    gemm_tc<4><<<gwo, 256>>>(hid, mw2, mb2, out, MLPH, BDIM, x1, msk, nullptr, nullptr);
}